// round 3
// baseline (speedup 1.0000x reference)
#include <cuda_runtime.h>
#include <cstddef>

#define Bv 32
#define Tv 512
#define Cv 8
#define Hv 256
#define Gv 1024

// ---------------- scratch (device globals: allocation-free) ----------------
__device__ float g_h1[(size_t)Tv * Cv * Bv * Hv];   // layer1 hidden states, 134 MB
__device__ float g_hbuf[2 * Cv * Bv * Hv];          // double-buffered h exchange, 512 KB
__device__ unsigned g_cnt[Cv];                      // per-channel barrier counters (zero-init)
__device__ unsigned g_sense[Cv];                    // per-channel barrier sense (zero-init)

// ---------------- math helpers ----------------
__device__ __forceinline__ float sig_(float x) {
    return __fdividef(1.0f, 1.0f + __expf(-x));
}
__device__ __forceinline__ float tanh_(float x) {
    float ax = fabsf(x);
    float e  = __expf(-2.0f * ax);
    float t  = __fdividef(1.0f - e, 1.0f + e);
    return copysignf(t, x);
}

// per-channel sense-reversing barrier across the 16 CTAs of a channel
__device__ __forceinline__ void chan_barrier(int c, unsigned &lsense) {
    __syncthreads();
    if (threadIdx.x == 0) {
        __threadfence();  // push this CTA's h writes to L2 (cumulative w/ bar.sync)
        unsigned a = atomicAdd(&g_cnt[c], 1u);
        if (a == 15u) {
            *(volatile unsigned*)&g_cnt[c] = 0u;
            __threadfence();
            *(volatile unsigned*)&g_sense[c] = lsense ^ 1u;
        } else {
            while (*(volatile unsigned*)&g_sense[c] == lsense) { __nanosleep(20); }
            __threadfence();  // acquire
        }
    }
    lsense ^= 1u;
    __syncthreads();
}

// ---------------- smem layout (floats), identical for both kernels ----------------
// Whh_s  [256][64]  k-major : 16384
// Wih_s  [256][64]  k-major : 16384 (layer2 only; allocated always)
// h_s    [32][256]          : 8192
// h1_s   [32][256]          : 8192 (layer2 only; allocated always)
// gsm    [32][64]           : 2048
// c_s    [512]              : 512
// bsum   [64]               : 64
// wih1s  [64]               : 64
// xs     [32]               : 32
// wlin_s [256]              : 256
// ored   [256]              : 256
#define SM_FLOATS (16384 + 16384 + 8192 + 8192 + 2048 + 512 + 64 + 64 + 32 + 256 + 256)
#define SM_BYTES  (SM_FLOATS * 4)

template <int LAYER>
__global__ __launch_bounds__(512, 1)
void lstm_kernel(const float* __restrict__ x,
                 const float* __restrict__ Wih,   // L1: Wih1 [C][G][1]; L2: Wih2 [C][G][H]
                 const float* __restrict__ Whh,   // [C][G][H]
                 const float* __restrict__ bih,   // [C][G]
                 const float* __restrict__ bhh,   // [C][G]
                 const float* __restrict__ Wlin,  // [C][H]   (L2)
                 const float* __restrict__ blin,  // [C]      (L2)
                 float* __restrict__ out)         // [B][T][C](L2)
{
    extern __shared__ float sm[];
    float* Whh_s  = sm;
    float* Wih_s  = Whh_s + 16384;
    float* h_s    = Wih_s + 16384;
    float* h1_s   = h_s   + Bv * Hv;
    float* gsm    = h1_s  + Bv * Hv;
    float* c_s    = gsm   + Bv * 64;
    float* bsum   = c_s   + 512;
    float* wih1s  = bsum  + 64;
    float* xs     = wih1s + 64;
    float* wlin_s = xs    + 32;
    float* ored   = wlin_s + 256;

    const int tid   = threadIdx.x;            // 0..511
    const int c     = blockIdx.x >> 4;        // channel
    const int rank  = blockIdx.x & 15;        // CTA within channel
    const int jbase = rank << 4;               // 16 hidden indices per CTA

    // ---- init: load weight slices (k-major in smem), biases, zero state ----
    for (int idx = tid; idx < 64 * Hv; idx += 512) {
        int k  = idx >> 6;     // 0..255
        int r  = idx & 63;     // local row 0..63
        int g  = r >> 4;
        int jl = r & 15;
        size_t grow = (size_t)c * Gv + g * Hv + (jbase + jl);
        Whh_s[k * 64 + r] = Whh[grow * Hv + k];
        if (LAYER == 2)
            Wih_s[k * 64 + r] = Wih[grow * Hv + k];
    }
    if (tid < 64) {
        int g = tid >> 4, jl = tid & 15;
        size_t gi = (size_t)c * Gv + g * Hv + (jbase + jl);
        bsum[tid] = bih[gi] + bhh[gi];
        if (LAYER == 1) wih1s[tid] = Wih[gi];   // Wih1[..,0]
    }
    if (LAYER == 2 && tid < Hv) wlin_s[tid] = Wlin[c * Hv + tid];
    for (int i = tid; i < Bv * Hv; i += 512) h_s[i] = 0.0f;
    c_s[tid] = 0.0f;
    __syncthreads();

    // ---- work decomposition: thread -> (b-quad, gate, j) ----
    const int bq  = tid >> 6;           // 0..7  (4 batch rows each)
    const int gg  = (tid >> 4) & 3;     // gate
    const int jj  = tid & 15;           // local hidden idx
    const int row = (gg << 4) | jj;     // 0..63 local gate-row
    const int b0  = bq << 2;

    unsigned lsense = 0;

    for (int t = 0; t < Tv; ++t) {
        // stage per-step inputs
        if (LAYER == 2) {
            const float4* src = (const float4*)(g_h1 + (size_t)(t * Cv + c) * Bv * Hv);
            #pragma unroll
            for (int i = 0; i < 4; ++i)
                ((float4*)h1_s)[tid + i * 512] = __ldg(src + tid + i * 512);
        } else {
            if (tid < Bv) xs[tid] = __ldg(&x[(size_t)tid * Tv * Cv + t * Cv + c]);
        }
        __syncthreads();   // h_s (from prev reload) + staged inputs ready

        // ---- gate mat-vecs: acc over 4 batch rows, full K=256 ----
        float a0 = 0.f, a1 = 0.f, a2 = 0.f, a3 = 0.f;
        {
            const float* h0p = h_s + (b0 + 0) * Hv;
            const float* h1p = h_s + (b0 + 1) * Hv;
            const float* h2p = h_s + (b0 + 2) * Hv;
            const float* h3p = h_s + (b0 + 3) * Hv;
            const float* wp  = Whh_s + row;
            const float* p0p = h1_s + (b0 + 0) * Hv;
            const float* p1p = h1_s + (b0 + 1) * Hv;
            const float* p2p = h1_s + (b0 + 2) * Hv;
            const float* p3p = h1_s + (b0 + 3) * Hv;
            const float* vp  = Wih_s + row;

            #pragma unroll 4
            for (int k = 0; k < Hv; k += 4) {
                float w0 = wp[(k + 0) * 64];
                float w1 = wp[(k + 1) * 64];
                float w2 = wp[(k + 2) * 64];
                float w3 = wp[(k + 3) * 64];
                float4 hv;
                hv = *(const float4*)(h0p + k);
                a0 = fmaf(hv.x, w0, fmaf(hv.y, w1, fmaf(hv.z, w2, fmaf(hv.w, w3, a0))));
                hv = *(const float4*)(h1p + k);
                a1 = fmaf(hv.x, w0, fmaf(hv.y, w1, fmaf(hv.z, w2, fmaf(hv.w, w3, a1))));
                hv = *(const float4*)(h2p + k);
                a2 = fmaf(hv.x, w0, fmaf(hv.y, w1, fmaf(hv.z, w2, fmaf(hv.w, w3, a2))));
                hv = *(const float4*)(h3p + k);
                a3 = fmaf(hv.x, w0, fmaf(hv.y, w1, fmaf(hv.z, w2, fmaf(hv.w, w3, a3))));

                if (LAYER == 2) {
                    float v0 = vp[(k + 0) * 64];
                    float v1 = vp[(k + 1) * 64];
                    float v2 = vp[(k + 2) * 64];
                    float v3 = vp[(k + 3) * 64];
                    float4 pv;
                    pv = *(const float4*)(p0p + k);
                    a0 = fmaf(pv.x, v0, fmaf(pv.y, v1, fmaf(pv.z, v2, fmaf(pv.w, v3, a0))));
                    pv = *(const float4*)(p1p + k);
                    a1 = fmaf(pv.x, v0, fmaf(pv.y, v1, fmaf(pv.z, v2, fmaf(pv.w, v3, a1))));
                    pv = *(const float4*)(p2p + k);
                    a2 = fmaf(pv.x, v0, fmaf(pv.y, v1, fmaf(pv.z, v2, fmaf(pv.w, v3, a2))));
                    pv = *(const float4*)(p3p + k);
                    a3 = fmaf(pv.x, v0, fmaf(pv.y, v1, fmaf(pv.z, v2, fmaf(pv.w, v3, a3))));
                }
            }
        }
        gsm[(b0 + 0) * 64 + row] = a0;
        gsm[(b0 + 1) * 64 + row] = a1;
        gsm[(b0 + 2) * 64 + row] = a2;
        gsm[(b0 + 3) * 64 + row] = a3;
        __syncthreads();

        // ---- activations + state update: one (b, j) unit per thread ----
        {
            int b  = tid >> 4;
            int j2 = tid & 15;
            float vi = gsm[b * 64 +       j2];
            float vf = gsm[b * 64 + 16 +  j2];
            float vg = gsm[b * 64 + 32 +  j2];
            float vo = gsm[b * 64 + 48 +  j2];
            if (LAYER == 1) {
                float xv = xs[b];
                vi = fmaf(xv, wih1s[     j2], vi + bsum[     j2]);
                vf = fmaf(xv, wih1s[16 + j2], vf + bsum[16 + j2]);
                vg = fmaf(xv, wih1s[32 + j2], vg + bsum[32 + j2]);
                vo = fmaf(xv, wih1s[48 + j2], vo + bsum[48 + j2]);
            } else {
                vi += bsum[     j2];
                vf += bsum[16 + j2];
                vg += bsum[32 + j2];
                vo += bsum[48 + j2];
            }
            float iv = sig_(vi), fv = sig_(vf), gv = tanh_(vg), ov = sig_(vo);
            float cn = fmaf(fv, c_s[tid], iv * gv);
            c_s[tid] = cn;
            float hn = ov * tanh_(cn);
            size_t hoff = ((size_t)c * Bv + b) * Hv + jbase + j2;
            g_hbuf[(size_t)(t & 1) * Cv * Bv * Hv + hoff] = hn;
            if (LAYER == 1)
                g_h1[((size_t)(t * Cv + c) * Bv + b) * Hv + jbase + j2] = hn;
        }

        chan_barrier(c, lsense);

        // ---- reload full h[t] for this channel (bypass L1: cross-CTA data) ----
        {
            const float4* src = (const float4*)(g_hbuf + (size_t)(t & 1) * Cv * Bv * Hv
                                                        + (size_t)c * Bv * Hv);
            #pragma unroll
            for (int i = 0; i < 4; ++i)
                ((float4*)h_s)[tid + i * 512] = __ldcg(src + tid + i * 512);
        }

        // ---- final linear head (layer2, rank-0 CTA only; uses fresh full h_s) ----
        if (LAYER == 2 && rank == 0) {
            __syncthreads();
            if (tid < 256) {
                int b = tid >> 3, kc = tid & 7;
                const float* hp = h_s + b * Hv + kc * 32;
                const float* wl = wlin_s + kc * 32;
                float s = 0.0f;
                #pragma unroll
                for (int k2 = 0; k2 < 32; ++k2) s = fmaf(hp[k2], wl[k2], s);
                ored[tid] = s;
            }
            __syncthreads();
            if (tid < 32) {
                float s = __ldg(&blin[c]);
                #pragma unroll
                for (int q = 0; q < 8; ++q) s += ored[tid * 8 + q];
                out[(size_t)tid * Tv * Cv + t * Cv + c] = s;
            }
        }
        // loop-top __syncthreads orders h_s reload before next compute
    }
}

// ---------------- launch ----------------
extern "C" void kernel_launch(void* const* d_in, const int* in_sizes, int n_in,
                              void* d_out, int out_size)
{
    const float* x    = (const float*)d_in[0];
    const float* Wih1 = (const float*)d_in[1];
    const float* Whh1 = (const float*)d_in[2];
    const float* bih1 = (const float*)d_in[3];
    const float* bhh1 = (const float*)d_in[4];
    const float* Wih2 = (const float*)d_in[5];
    const float* Whh2 = (const float*)d_in[6];
    const float* bih2 = (const float*)d_in[7];
    const float* bhh2 = (const float*)d_in[8];
    const float* Wlin = (const float*)d_in[9];
    const float* blin = (const float*)d_in[10];
    float* out = (float*)d_out;

    (void)in_sizes; (void)n_in; (void)out_size;

    cudaFuncSetAttribute(lstm_kernel<1>, cudaFuncAttributeMaxDynamicSharedMemorySize, SM_BYTES);
    cudaFuncSetAttribute(lstm_kernel<2>, cudaFuncAttributeMaxDynamicSharedMemorySize, SM_BYTES);

    lstm_kernel<1><<<128, 512, SM_BYTES>>>(x, Wih1, Whh1, bih1, bhh1,
                                           nullptr, nullptr, nullptr);
    lstm_kernel<2><<<128, 512, SM_BYTES>>>(nullptr, Wih2, Whh2, bih2, bhh2,
                                           Wlin, blin, out);
}

// round 4
// speedup vs baseline: 1.4855x; 1.4855x over previous
#include <cuda_runtime.h>
#include <cstddef>
#include <cstring>

#define Bv 32
#define Tv 512
#define Cv 8
#define Hv 256
#define Gv 1024

// ---------------- scratch (device globals: allocation-free) ----------------
__device__ float g_h1[(size_t)Tv * Cv * Hv * Bv];   // layer1 hidden, [T][C][H][B], 134 MB
__device__ float g_hbuf[2 * Cv * Hv * Bv];          // h exchange, [2][C][H][B]
__device__ unsigned g_cnt[Cv];                      // per-channel barrier counters
__device__ unsigned g_sense[Cv];                    // per-channel barrier sense

// ---------------- math helpers ----------------
__device__ __forceinline__ float sig_(float x) {
    return __fdividef(1.0f, 1.0f + __expf(-x));
}
__device__ __forceinline__ float tanh_(float x) {
    float ax = fabsf(x);
    float e  = __expf(-2.0f * ax);
    float t  = __fdividef(1.0f - e, 1.0f + e);
    return copysignf(t, x);
}
__device__ __forceinline__ float2 u2f(unsigned long long u) {
    float2 f; memcpy(&f, &u, 8); return f;
}

// packed fp32x2 FMA (FFMA2) and operand duplication
#define FMA2(acc, h, w) asm("fma.rn.f32x2 %0, %1, %2, %0;" : "+l"(acc) : "l"(h), "l"(w))
#define PACK2(d, s)     asm("mov.b64 %0, {%1, %1};" : "=l"(d) : "f"(s))

// per-channel sense-reversing barrier across the 16 CTAs of a channel
__device__ __forceinline__ void chan_barrier(int c, unsigned &lsense) {
    __syncthreads();
    if (threadIdx.x == 0) {
        __threadfence();
        unsigned a = atomicAdd(&g_cnt[c], 1u);
        if (a == 15u) {
            *(volatile unsigned*)&g_cnt[c] = 0u;
            __threadfence();
            *(volatile unsigned*)&g_sense[c] = lsense ^ 1u;
        } else {
            while (*(volatile unsigned*)&g_sense[c] == lsense) { __nanosleep(20); }
            __threadfence();
        }
    }
    lsense ^= 1u;
    __syncthreads();
}

// ---------------- smem layout (floats) ----------------
// Whh_s [256][64] k-major : 16384
// Wih_s [256][64] k-major : 16384 (layer2)
// h_s   [256][32] k-major transposed : 8192
// h1_s  [256][32] : 8192 (layer2)
// gsm   [32][64]  : 2048   (final gate sums, [b][row])
// part0 [32][64]  : 2048   (kq=2 partials)
// part1 [32][64]  : 2048   (kq=3 partials)
// c_s 512, bsum 64, wih1s 64, xs 32, wlin_s 256, ored 256
#define SM_FLOATS (16384 + 16384 + 8192 + 8192 + 2048 + 2048 + 2048 + 512 + 64 + 64 + 32 + 256 + 256)
#define SM_BYTES  (SM_FLOATS * 4)

template <int LAYER>
__global__ __launch_bounds__(512, 1)
void lstm_kernel(const float* __restrict__ x,
                 const float* __restrict__ Wih,   // L1: [C][G][1]; L2: [C][G][H]
                 const float* __restrict__ Whh,   // [C][G][H]
                 const float* __restrict__ bih,   // [C][G]
                 const float* __restrict__ bhh,   // [C][G]
                 const float* __restrict__ Wlin,  // [C][H]  (L2)
                 const float* __restrict__ blin,  // [C]     (L2)
                 float* __restrict__ out)         // [B][T][C] (L2)
{
    extern __shared__ float sm[];
    float* Whh_s  = sm;
    float* Wih_s  = Whh_s + 16384;
    float* h_s    = Wih_s + 16384;
    float* h1_s   = h_s   + 8192;
    float* gsm    = h1_s  + 8192;
    float* part0  = gsm   + 2048;
    float* part1  = part0 + 2048;
    float* c_s    = part1 + 2048;
    float* bsum   = c_s   + 512;
    float* wih1s  = bsum  + 64;
    float* xs     = wih1s + 64;
    float* wlin_s = xs    + 32;
    float* ored   = wlin_s + 256;

    const int tid   = threadIdx.x;
    const int c     = blockIdx.x >> 4;
    const int rank  = blockIdx.x & 15;
    const int jbase = rank << 4;

    // compute decomposition: warp = 32 row-pairs, fixed (oct, kq)
    const int rp  = tid & 31;          // row-pair 0..31 -> rows 2rp, 2rp+1
    const int oct = (tid >> 5) & 3;    // batch octet 0..3 -> batches oct*8..+7
    const int kq  = tid >> 7;          // k-quarter 0..3 -> k in [kq*64, kq*64+64)

    // ---- init: weights k-major, biases, zero state ----
    for (int idx = tid; idx < 64 * Hv; idx += 512) {
        int k  = idx >> 6;
        int r  = idx & 63;
        int g  = r >> 4;
        int jl = r & 15;
        size_t grow = (size_t)c * Gv + g * Hv + (jbase + jl);
        Whh_s[k * 64 + r] = Whh[grow * Hv + k];
        if (LAYER == 2)
            Wih_s[k * 64 + r] = Wih[grow * Hv + k];
    }
    if (tid < 64) {
        int g = tid >> 4, jl = tid & 15;
        size_t gi = (size_t)c * Gv + g * Hv + (jbase + jl);
        bsum[tid] = bih[gi] + bhh[gi];
        if (LAYER == 1) wih1s[tid] = Wih[gi];
    }
    if (LAYER == 2 && tid < Hv) wlin_s[tid] = Wlin[c * Hv + tid];
    for (int i = tid; i < Hv * Bv; i += 512) h_s[i] = 0.0f;
    c_s[tid] = 0.0f;
    __syncthreads();

    const float blin_c = (LAYER == 2) ? __ldg(&blin[c]) : 0.0f;
    unsigned lsense = 0;

    for (int t = 0; t < Tv; ++t) {
        // ---- stage per-step inputs ----
        if (LAYER == 2) {
            const float4* src = (const float4*)(g_h1 + ((size_t)t * Cv + c) * (Hv * Bv));
            float4* dst = (float4*)h1_s;
            #pragma unroll
            for (int i = 0; i < 4; ++i)
                dst[tid + i * 512] = __ldg(src + tid + i * 512);
        } else {
            if (tid < Bv) xs[tid] = __ldg(&x[(size_t)tid * Tv * Cv + t * Cv + c]);
        }
        __syncthreads();

        // ---- gate mat-vecs: rows {2rp,2rp+1} x batches oct*8..+7 over k-quarter ----
        unsigned long long A[8], Bk[8];
        #pragma unroll
        for (int i = 0; i < 8; ++i) { A[i] = 0ull; Bk[i] = 0ull; }
        {
            const float* wh  = Whh_s + kq * 64 * 64 + 2 * rp;
            const float* hpp = h_s   + kq * 64 * 32 + oct * 8;
            const float* wi  = Wih_s + kq * 64 * 64 + 2 * rp;
            const float* ppp = h1_s  + kq * 64 * 32 + oct * 8;

            #pragma unroll 4
            for (int kk = 0; kk < 64; ++kk) {
                float2 wv = *(const float2*)wh;  wh += 64;
                unsigned long long w0, w1;
                PACK2(w0, wv.x); PACK2(w1, wv.y);
                ulonglong2 ha = *(const ulonglong2*)hpp;
                ulonglong2 hb = *(const ulonglong2*)(hpp + 4);  hpp += 32;
                FMA2(A[0], ha.x, w0); FMA2(A[1], ha.y, w0);
                FMA2(A[2], hb.x, w0); FMA2(A[3], hb.y, w0);
                FMA2(A[4], ha.x, w1); FMA2(A[5], ha.y, w1);
                FMA2(A[6], hb.x, w1); FMA2(A[7], hb.y, w1);

                if (LAYER == 2) {
                    float2 vv = *(const float2*)wi;  wi += 64;
                    unsigned long long v0, v1;
                    PACK2(v0, vv.x); PACK2(v1, vv.y);
                    ulonglong2 pa = *(const ulonglong2*)ppp;
                    ulonglong2 pb = *(const ulonglong2*)(ppp + 4);  ppp += 32;
                    FMA2(Bk[0], pa.x, v0); FMA2(Bk[1], pa.y, v0);
                    FMA2(Bk[2], pb.x, v0); FMA2(Bk[3], pb.y, v0);
                    FMA2(Bk[4], pa.x, v1); FMA2(Bk[5], pa.y, v1);
                    FMA2(Bk[6], pb.x, v1); FMA2(Bk[7], pb.y, v1);
                }
            }
        }
        // merge hh + ih accumulators
        float2 R[8];
        #pragma unroll
        for (int i = 0; i < 8; ++i) {
            float2 fa = u2f(A[i]);
            if (LAYER == 2) { float2 fb = u2f(Bk[i]); fa.x += fb.x; fa.y += fb.y; }
            R[i] = fa;
        }

        // ---- cross-kq reduction: kq 0->gsm, 2->part0, 3->part1; kq1 combines ----
        {
            float* dst = (kq == 0) ? gsm : (kq == 2) ? part0 : (kq == 3) ? part1 : (float*)0;
            if (dst) {
                #pragma unroll
                for (int p = 0; p < 4; ++p) {
                    int b = oct * 8 + 2 * p;
                    *(float2*)(dst + b * 64 + 2 * rp)       = make_float2(R[p].x, R[4 + p].x);
                    *(float2*)(dst + (b + 1) * 64 + 2 * rp) = make_float2(R[p].y, R[4 + p].y);
                }
            }
        }
        __syncthreads();
        if (kq == 1) {
            #pragma unroll
            for (int p = 0; p < 4; ++p) {
                int b = oct * 8 + 2 * p;
                float2* g0 = (float2*)(gsm + b * 64 + 2 * rp);
                float2* g1 = (float2*)(gsm + (b + 1) * 64 + 2 * rp);
                float2 p00 = *(float2*)(part0 + b * 64 + 2 * rp);
                float2 p01 = *(float2*)(part0 + (b + 1) * 64 + 2 * rp);
                float2 p10 = *(float2*)(part1 + b * 64 + 2 * rp);
                float2 p11 = *(float2*)(part1 + (b + 1) * 64 + 2 * rp);
                float2 a = *g0, bb = *g1;
                a.x  += p00.x + p10.x + R[p].x;
                a.y  += p00.y + p10.y + R[4 + p].x;
                bb.x += p01.x + p11.x + R[p].y;
                bb.y += p01.y + p11.y + R[4 + p].y;
                *g0 = a; *g1 = bb;
            }
        }
        __syncthreads();

        // ---- activations + state update: thread -> (b = tid>>4, j2 = tid&15) ----
        {
            int b  = tid >> 4;
            int j2 = tid & 15;
            const float* gr = gsm + b * 64;
            float vi = gr[      j2] + bsum[      j2];
            float vf = gr[16 + j2] + bsum[16 + j2];
            float vg = gr[32 + j2] + bsum[32 + j2];
            float vo = gr[48 + j2] + bsum[48 + j2];
            if (LAYER == 1) {
                float xv = xs[b];
                vi = fmaf(xv, wih1s[     j2], vi);
                vf = fmaf(xv, wih1s[16 + j2], vf);
                vg = fmaf(xv, wih1s[32 + j2], vg);
                vo = fmaf(xv, wih1s[48 + j2], vo);
            }
            float iv = sig_(vi), fv = sig_(vf), gv = tanh_(vg), ov = sig_(vo);
            float cn = fmaf(fv, c_s[tid], iv * gv);
            c_s[tid] = cn;
            float hn = ov * tanh_(cn);
            size_t hoff = ((size_t)c * Hv + jbase + j2) * Bv + b;   // [C][H][B]
            g_hbuf[(size_t)(t & 1) * (Cv * Hv * Bv) + hoff] = hn;
            if (LAYER == 1)
                g_h1[(((size_t)t * Cv + c) * Hv + jbase + j2) * Bv + b] = hn;
        }

        chan_barrier(c, lsense);

        // ---- reload full h[t] for this channel into transposed h_s[k][b] ----
        {
            const float4* src = (const float4*)(g_hbuf + (size_t)(t & 1) * (Cv * Hv * Bv)
                                                        + (size_t)c * Hv * Bv);
            float4* dst = (float4*)h_s;
            #pragma unroll
            for (int i = 0; i < 4; ++i)
                dst[tid + i * 512] = __ldcg(src + tid + i * 512);
        }

        // ---- final linear head (layer2, rank-0 CTA) ----
        if (LAYER == 2 && rank == 0) {
            __syncthreads();     // h_s reload visible
            if (tid < 256) {
                int w = tid >> 5, b = tid & 31;      // warp w: k-slice, lane = batch
                const float* hp = h_s + w * 32 * 32 + b;
                const float* wl = wlin_s + w * 32;
                float s = 0.0f;
                #pragma unroll
                for (int k2 = 0; k2 < 32; ++k2)
                    s = fmaf(hp[k2 * 32], wl[k2], s);
                ored[w * 32 + b] = s;
            }
            __syncthreads();
            if (tid < 32) {
                float s = blin_c;
                #pragma unroll
                for (int w = 0; w < 8; ++w) s += ored[w * 32 + tid];
                out[(size_t)tid * Tv * Cv + t * Cv + c] = s;
            }
        }
        // loop-top __syncthreads orders h_s reload before next compute
    }
}

// ---------------- launch ----------------
extern "C" void kernel_launch(void* const* d_in, const int* in_sizes, int n_in,
                              void* d_out, int out_size)
{
    const float* x    = (const float*)d_in[0];
    const float* Wih1 = (const float*)d_in[1];
    const float* Whh1 = (const float*)d_in[2];
    const float* bih1 = (const float*)d_in[3];
    const float* bhh1 = (const float*)d_in[4];
    const float* Wih2 = (const float*)d_in[5];
    const float* Whh2 = (const float*)d_in[6];
    const float* bih2 = (const float*)d_in[7];
    const float* bhh2 = (const float*)d_in[8];
    const float* Wlin = (const float*)d_in[9];
    const float* blin = (const float*)d_in[10];
    float* out = (float*)d_out;

    (void)in_sizes; (void)n_in; (void)out_size;

    cudaFuncSetAttribute(lstm_kernel<1>, cudaFuncAttributeMaxDynamicSharedMemorySize, SM_BYTES);
    cudaFuncSetAttribute(lstm_kernel<2>, cudaFuncAttributeMaxDynamicSharedMemorySize, SM_BYTES);

    lstm_kernel<1><<<128, 512, SM_BYTES>>>(x, Wih1, Whh1, bih1, bhh1,
                                           nullptr, nullptr, nullptr);
    lstm_kernel<2><<<128, 512, SM_BYTES>>>(nullptr, Wih2, Whh2, bih2, bhh2,
                                           Wlin, blin, out);
}